// round 2
// baseline (speedup 1.0000x reference)
#include <cuda_runtime.h>
#include <cuda_bf16.h>
#include <math.h>

// Problem constants (K=eigenpairs, C=channels fixed by the dataset)
#define KDIM 256
#define CDIM 128
#define P1_BLOCKS 148   // split-N chunks == grid of phase 1 == one wave

// Scratch (device globals: no allocation APIs allowed)
__device__ float g_part[P1_BLOCKS * KDIM * CDIM];   // ~19.4 MB partials
__device__ float g_xs[KDIM * CDIM];                 // scaled spectrum [K][C]

// ---------- packed f32x2 helpers ----------
typedef unsigned long long ull;

__device__ __forceinline__ ull pack2(float lo, float hi) {
    ull r;
    asm("mov.b64 %0, {%1, %2};" : "=l"(r) : "f"(lo), "f"(hi));
    return r;
}
__device__ __forceinline__ void unpack2(ull v, float& lo, float& hi) {
    asm("mov.b64 {%0, %1}, %2;" : "=f"(lo), "=f"(hi) : "l"(v));
}
__device__ __forceinline__ void ffma2(ull& d, ull a, ull b) {
    asm("fma.rn.f32x2 %0, %1, %2, %0;" : "+l"(d) : "l"(a), "l"(b));
}

// =====================================================================
// Phase 1: partial[b] = evecs[nb:ne]^T @ x[nb:ne]   -> [256 x 128]
// 512 threads, thread grid 32(k) x 16(c), micro-tile 8x8, TN=16
// =====================================================================
__global__ void __launch_bounds__(512, 1)
phase1_kernel(const float* __restrict__ evecs, const float* __restrict__ x,
              int N, int chunk)
{
    __shared__ float As[16][KDIM];   // evecs rows  (16 KB)
    __shared__ float Bs[16][CDIM];   // x rows      (8 KB)

    const int tid = threadIdx.x;
    const int ty = tid >> 4;   // 0..31  -> k rows ty*8..ty*8+7
    const int tx = tid & 15;   // 0..15  -> c cols tx*8..tx*8+7

    ull acc[8][4];
    #pragma unroll
    for (int j = 0; j < 8; j++)
        #pragma unroll
        for (int c = 0; c < 4; c++) acc[j][c] = 0ull;

    const int nb = blockIdx.x * chunk;
    const int ne = min(N, nb + chunk);

    for (int n0 = nb; n0 < ne; n0 += 16) {
        // --- load A tile: 16 x 256 floats = 1024 float4, 2 per thread ---
        #pragma unroll
        for (int it = 0; it < 2; it++) {
            int idx = tid + it * 512;      // 0..1023
            int r  = idx >> 6;             // row 0..15
            int kq = idx & 63;             // float4 index in row
            float4 v = make_float4(0.f, 0.f, 0.f, 0.f);
            if (n0 + r < ne)
                v = *(const float4*)(evecs + (size_t)(n0 + r) * KDIM + kq * 4);
            *(float4*)&As[r][kq * 4] = v;
        }
        // --- load B tile: 16 x 128 floats = 512 float4, 1 per thread ---
        {
            int r  = tid >> 5;             // row 0..15
            int cq = tid & 31;             // float4 index in row
            float4 v = make_float4(0.f, 0.f, 0.f, 0.f);
            if (n0 + r < ne)
                v = *(const float4*)(x + (size_t)(n0 + r) * CDIM + cq * 4);
            *(float4*)&Bs[r][cq * 4] = v;
        }
        __syncthreads();

        #pragma unroll
        for (int i = 0; i < 16; i++) {
            float4 a0 = *(const float4*)&As[i][ty * 8];
            float4 a1 = *(const float4*)&As[i][ty * 8 + 4];
            float4 b0 = *(const float4*)&Bs[i][tx * 8];
            float4 b1 = *(const float4*)&Bs[i][tx * 8 + 4];
            ull aa[8];
            aa[0] = pack2(a0.x, a0.x); aa[1] = pack2(a0.y, a0.y);
            aa[2] = pack2(a0.z, a0.z); aa[3] = pack2(a0.w, a0.w);
            aa[4] = pack2(a1.x, a1.x); aa[5] = pack2(a1.y, a1.y);
            aa[6] = pack2(a1.z, a1.z); aa[7] = pack2(a1.w, a1.w);
            ull bb[4];
            bb[0] = pack2(b0.x, b0.y); bb[1] = pack2(b0.z, b0.w);
            bb[2] = pack2(b1.x, b1.y); bb[3] = pack2(b1.z, b1.w);
            #pragma unroll
            for (int j = 0; j < 8; j++)
                #pragma unroll
                for (int c = 0; c < 4; c++)
                    ffma2(acc[j][c], aa[j], bb[c]);
        }
        __syncthreads();
    }

    // store partials (full tile written, no init needed)
    float* base = g_part + (size_t)blockIdx.x * (KDIM * CDIM);
    #pragma unroll
    for (int j = 0; j < 8; j++) {
        int k = ty * 8 + j;
        #pragma unroll
        for (int c = 0; c < 4; c++) {
            int cc = tx * 8 + c * 2;
            *(ull*)(base + k * CDIM + cc) = acc[j][c];
        }
    }
}

// =====================================================================
// Reduce: xs[k][c] = exp(-evals[k]*t) * sum_b part[b][k][c]
// =====================================================================
__global__ void reduce_kernel(const float* __restrict__ evals,
                              const float* __restrict__ dt)
{
    int idx = blockIdx.x * 256 + threadIdx.x;   // 0..32767
    float s0 = 0.f, s1 = 0.f, s2 = 0.f, s3 = 0.f;
    int b = 0;
    #pragma unroll 4
    for (; b + 4 <= P1_BLOCKS; b += 4) {
        s0 += g_part[(size_t)(b + 0) * (KDIM * CDIM) + idx];
        s1 += g_part[(size_t)(b + 1) * (KDIM * CDIM) + idx];
        s2 += g_part[(size_t)(b + 2) * (KDIM * CDIM) + idx];
        s3 += g_part[(size_t)(b + 3) * (KDIM * CDIM) + idx];
    }
    for (; b < P1_BLOCKS; b++)
        s0 += g_part[(size_t)b * (KDIM * CDIM) + idx];
    float s = (s0 + s1) + (s2 + s3);

    int k = idx >> 7;
    float t = fmaxf(dt[0], 1e-8f);
    g_xs[idx] = expf(-evals[k] * t) * s;
}

// =====================================================================
// Phase 2: out = evecs @ xs.  Whole xs (128 KB) in dynamic smem.
// 512 threads = 16 warps; each warp owns 8 output rows x 128 channels.
// =====================================================================
__global__ void __launch_bounds__(512, 1)
phase2_kernel(const float* __restrict__ evecs, float* __restrict__ out, int N)
{
    extern __shared__ float xs_s[];   // [256][128]

    const int tid = threadIdx.x;
    // load xs into smem: 8192 float4 / 512 threads = 16 each
    #pragma unroll
    for (int i = 0; i < 16; i++) {
        int idx = tid + i * 512;
        *(float4*)&xs_s[idx * 4] = *(const float4*)&g_xs[idx * 4];
    }
    __syncthreads();

    const int warp = tid >> 5;
    const int lane = tid & 31;
    const int ngroups = (N + 7) >> 3;     // groups of 8 rows

    for (int g = blockIdx.x * 16 + warp; g < ngroups; g += gridDim.x * 16) {
        const int row0 = g * 8;
        // per-row base pointers; invalid rows alias row 0 (safe load, no store)
        const float* ep[8];
        #pragma unroll
        for (int r = 0; r < 8; r++) {
            int row = row0 + r;
            ep[r] = evecs + (size_t)(row < N ? row : 0) * KDIM;
        }

        ull acc[8][2];
        #pragma unroll
        for (int r = 0; r < 8; r++) { acc[r][0] = 0ull; acc[r][1] = 0ull; }

        for (int k0 = 0; k0 < KDIM; k0 += 4) {
            float4 ev[8];
            #pragma unroll
            for (int r = 0; r < 8; r++)
                ev[r] = *(const float4*)(ep[r] + k0);   // uniform across warp

            #pragma unroll
            for (int q = 0; q < 4; q++) {
                float4 xv = *(const float4*)&xs_s[(k0 + q) * CDIM + lane * 4];
                ull b0 = pack2(xv.x, xv.y);
                ull b1 = pack2(xv.z, xv.w);
                #pragma unroll
                for (int r = 0; r < 8; r++) {
                    float e = (q == 0) ? ev[r].x : (q == 1) ? ev[r].y
                             : (q == 2) ? ev[r].z : ev[r].w;
                    ull ea = pack2(e, e);
                    ffma2(acc[r][0], ea, b0);
                    ffma2(acc[r][1], ea, b1);
                }
            }
        }

        #pragma unroll
        for (int r = 0; r < 8; r++) {
            int row = row0 + r;
            if (row < N) {
                float4 o;
                unpack2(acc[r][0], o.x, o.y);
                unpack2(acc[r][1], o.z, o.w);
                *(float4*)(out + (size_t)row * CDIM + lane * 4) = o;
            }
        }
    }
}

// =====================================================================
extern "C" void kernel_launch(void* const* d_in, const int* in_sizes, int n_in,
                              void* d_out, int out_size)
{
    // Resolve inputs by element count (robust to ordering):
    // evecs = N*K (largest), x = N*C, evals = 256, dt = 1
    const float* x = nullptr;
    const float* evals = nullptr;
    const float* evecs = nullptr;
    const float* dt = nullptr;
    long big_a = -1, big_b = -1; int ia = -1, ib = -1;
    for (int i = 0; i < n_in; i++) {
        long sz = in_sizes[i];
        if (sz == 1)            dt    = (const float*)d_in[i];
        else if (sz == KDIM)    evals = (const float*)d_in[i];
        else {
            if (sz > big_a) { big_b = big_a; ib = ia; big_a = sz; ia = i; }
            else if (sz > big_b) { big_b = sz; ib = i; }
        }
    }
    evecs = (const float*)d_in[ia];   // largest  = N*K
    x     = (const float*)d_in[ib];   // second   = N*C
    const int N = (int)(big_b / CDIM);

    const int chunk = (N + P1_BLOCKS - 1) / P1_BLOCKS;

    phase1_kernel<<<P1_BLOCKS, 512>>>(evecs, x, N, chunk);
    reduce_kernel<<<(KDIM * CDIM) / 256, 256>>>(evals, dt);

    cudaFuncSetAttribute(phase2_kernel,
                         cudaFuncAttributeMaxDynamicSharedMemorySize,
                         KDIM * CDIM * (int)sizeof(float));
    phase2_kernel<<<148, 512, KDIM * CDIM * sizeof(float)>>>(evecs,
                                                             (float*)d_out, N);
}

// round 4
// speedup vs baseline: 1.5400x; 1.5400x over previous
#include <cuda_runtime.h>
#include <cuda_bf16.h>
#include <cstdint>
#include <math.h>

#define KDIM 256
#define CDIM 128
#define P1_BLOCKS 148

// Scratch (device globals; no allocation allowed)
__device__ float g_part[P1_BLOCKS * KDIM * CDIM];   // phase1 partials (fp32)
__device__ float g_xsB[KDIM * CDIM];                // spectrum in B-fragment layout (tf32 bits)

// ---------------- tf32 + mma helpers (sm_80-level PTX only) ----------------
__device__ __forceinline__ uint32_t tf32r(float x) {
    uint32_t u; asm("cvt.rna.tf32.f32 %0, %1;" : "=r"(u) : "f"(x)); return u;
}
__device__ __forceinline__ void mma8(float* d, const uint32_t* a, const uint32_t* b) {
    asm volatile(
        "mma.sync.aligned.m16n8k8.row.col.f32.tf32.tf32.f32 "
        "{%0,%1,%2,%3}, {%4,%5,%6,%7}, {%8,%9}, {%0,%1,%2,%3};"
        : "+f"(d[0]), "+f"(d[1]), "+f"(d[2]), "+f"(d[3])
        : "r"(a[0]), "r"(a[1]), "r"(a[2]), "r"(a[3]), "r"(b[0]), "r"(b[1]));
}

// Fragment maps (m16n8k8):
//  A value (mL 0..15, kL 0..7): lane = (mL%8)*4 + (kL%4), reg = mL/8 + 2*(kL/4)
//  B value (kL 0..7,  nL 0..7): lane = nL*4 + (kL%4),     reg = kL/4
//  D value (mL, nL): c0,c1 -> row=lane/4,  col=2*(lane%4)+{0,1}; c2,c3 -> row+8

// =====================================================================
// Phase 1: partial[b] = evecs[nb:ne]^T @ x[nb:ne]  -> [256(k) x 128(c)]
// GEMM view: M=256 (eigen), N=128 (chan), reduction = nodes.
// 512 threads = 16 warps (4m x 4n), warp tile 64x32, node-chunks of 32.
// Dynamic smem: Afrag 2x32KB, Bfrag 2x16KB = 96KB.
// =====================================================================
__global__ void __launch_bounds__(512, 1)
phase1_kernel(const float* __restrict__ E, const float* __restrict__ X,
              int N, int chunk)
{
    extern __shared__ uint32_t sm[];
    uint32_t* Af = sm;              // [2][4 k8][16 mt][32 lane][4 reg]
    uint32_t* Bf = sm + 16384;      // [2][4 k8][16 ct][32 lane][2 reg]

    const int tid = threadIdx.x;
    const int warp = tid >> 5, lane = tid & 31;
    const int wm = warp >> 2;       // 0..3 -> m0 = wm*64
    const int wn = warp & 3;        // 0..3 -> n0 = wn*32

    float d[4][4][4];
    #pragma unroll
    for (int i = 0; i < 4; i++)
        #pragma unroll
        for (int j = 0; j < 4; j++)
            #pragma unroll
            for (int q = 0; q < 4; q++) d[i][j][q] = 0.f;

    const int nb = blockIdx.x * chunk;
    const int ne = min(N, nb + chunk);
    const int niter = (ne - nb + 31) >> 5;

    float4 curA[4], curB[2];

    // regs load for node-chunk starting at s0
    auto loadc = [&](int s0, float4* A4, float4* B2) {
        #pragma unroll
        for (int it = 0; it < 4; it++) {
            int fid = tid + it * 512;         // 0..2047
            int r = fid >> 6, j = fid & 63;   // node-in-chunk, m-float4
            int node = s0 + r;
            A4[it] = (node < ne) ? *(const float4*)(E + (size_t)node * KDIM + 4 * j)
                                 : make_float4(0.f, 0.f, 0.f, 0.f);
        }
        #pragma unroll
        for (int it = 0; it < 2; it++) {
            int fid = tid + it * 512;         // 0..1023
            int r = fid >> 5, j = fid & 31;
            int node = s0 + r;
            B2[it] = (node < ne) ? *(const float4*)(X + (size_t)node * CDIM + 4 * j)
                                 : make_float4(0.f, 0.f, 0.f, 0.f);
        }
    };

    loadc(nb, curA, curB);

    for (int itn = 0; itn < niter; itn++) {
        const int buf = itn & 1;
        float4 nxtA[4], nxtB[2];
        if (itn + 1 < niter) loadc(nb + (itn + 1) * 32, nxtA, nxtB);

        // scatter-store fragments (tf32-rounded)
        uint32_t* Ab = Af + buf * 8192;
        uint32_t* Bb = Bf + buf * 4096;
        #pragma unroll
        for (int it = 0; it < 4; it++) {
            int fid = tid + it * 512;
            int r = fid >> 6, j = fid & 63;
            int k8 = r >> 3, kL = r & 7, mt = j >> 2;
            uint32_t base = (uint32_t)((k8 * 16 + mt) * 32) * 4
                          + ((j >> 1) & 1) + 2 * (kL >> 2);
            uint32_t lbase = (uint32_t)(16 * (j & 1) + (kL & 3)) * 4;
            const float* v = (const float*)&curA[it];
            #pragma unroll
            for (int q = 0; q < 4; q++)
                Ab[base + (lbase + 4u * q) * 0 + ((16 * (j & 1) + 4 * q + (kL & 3)) * 4)] = tf32r(v[q]);
        }
        #pragma unroll
        for (int it = 0; it < 2; it++) {
            int fid = tid + it * 512;
            int r = fid >> 5, j = fid & 31;
            int k8 = r >> 3, kL = r & 7, ct = j >> 1;
            uint32_t base = (uint32_t)((k8 * 16 + ct) * 32) * 2 + (kL >> 2);
            const float* v = (const float*)&curB[it];
            #pragma unroll
            for (int q = 0; q < 4; q++)
                Bb[base + (uint32_t)(16 * (j & 1) + 4 * q + (kL & 3)) * 2] = tf32r(v[q]);
        }
        __syncthreads();

        // compute: 4 k8-steps
        #pragma unroll
        for (int k8 = 0; k8 < 4; k8++) {
            uint32_t a[4][4], b[4][2];
            #pragma unroll
            for (int i = 0; i < 4; i++) {
                uint4 av = *(const uint4*)(Ab + ((k8 * 16 + wm * 4 + i) * 32 + lane) * 4);
                a[i][0] = av.x; a[i][1] = av.y; a[i][2] = av.z; a[i][3] = av.w;
            }
            #pragma unroll
            for (int j = 0; j < 4; j++) {
                uint2 bv = *(const uint2*)(Bb + ((k8 * 16 + wn * 4 + j) * 32 + lane) * 2);
                b[j][0] = bv.x; b[j][1] = bv.y;
            }
            #pragma unroll
            for (int i = 0; i < 4; i++)
                #pragma unroll
                for (int j = 0; j < 4; j++)
                    mma8(d[i][j], a[i], b[j]);
        }
        __syncthreads();

        #pragma unroll
        for (int it = 0; it < 4; it++) curA[it] = nxtA[it];
        curB[0] = nxtB[0]; curB[1] = nxtB[1];
    }

    // epilogue: write fp32 partials
    float* base = g_part + (size_t)blockIdx.x * (KDIM * CDIM);
    const int rql = lane >> 2, cql = (lane & 3) * 2;
    #pragma unroll
    for (int i = 0; i < 4; i++) {
        int row = wm * 64 + i * 16 + rql;
        #pragma unroll
        for (int j = 0; j < 4; j++) {
            int col = wn * 32 + j * 8 + cql;
            *(float2*)(base + row * CDIM + col)       = make_float2(d[i][j][0], d[i][j][1]);
            *(float2*)(base + (row + 8) * CDIM + col) = make_float2(d[i][j][2], d[i][j][3]);
        }
    }
}

// =====================================================================
// Reduce: xs[k][c] = exp(-evals[k]*t) * sum_b part[b][k][c]
// Output written directly in B-fragment layout (tf32 bits) for phase 2.
// =====================================================================
__global__ void reduce_kernel(const float* __restrict__ evals,
                              const float* __restrict__ dt)
{
    int idx = blockIdx.x * 256 + threadIdx.x;   // k*128 + c
    float s0 = 0.f, s1 = 0.f, s2 = 0.f, s3 = 0.f;
    int b = 0;
    for (; b + 4 <= P1_BLOCKS; b += 4) {
        s0 += g_part[(size_t)(b + 0) * (KDIM * CDIM) + idx];
        s1 += g_part[(size_t)(b + 1) * (KDIM * CDIM) + idx];
        s2 += g_part[(size_t)(b + 2) * (KDIM * CDIM) + idx];
        s3 += g_part[(size_t)(b + 3) * (KDIM * CDIM) + idx];
    }
    for (; b < P1_BLOCKS; b++) s0 += g_part[(size_t)b * (KDIM * CDIM) + idx];
    float s = (s0 + s1) + (s2 + s3);

    int k = idx >> 7, c = idx & 127;
    float t = fmaxf(dt[0], 1e-8f);
    float v = expf(-evals[k] * t) * s;

    // B-fragment address: tile (k8=k/8, ct=c/8), lane=(c%8)*4+(k%4), reg=(k%8)/4
    int k8 = k >> 3, kL = k & 7, ct = c >> 3, cL = c & 7;
    uint32_t addr = (uint32_t)(((k8 * 16 + ct) * 32 + cL * 4 + (kL & 3)) * 2 + (kL >> 2));
    g_xsB[addr] = __uint_as_float(tf32r(v));
}

// =====================================================================
// Phase 2: out[m,c] = sum_k E[m,k] * xs[k,c]
// M-tile 128, N=128, K=256. 256 threads = 8 warps (2m x 4n), warp 64x32.
// smem: Bfull frag 128KB @0 | Afrag 2x32KB @32768 u32. Total 192KB.
// =====================================================================
__global__ void __launch_bounds__(256, 1)
phase2_kernel(const float* __restrict__ E, float* __restrict__ out, int N)
{
    extern __shared__ uint32_t sm[];
    uint32_t* Bfull = sm;            // [32 k8][16 ct][32 lane][2]
    uint32_t* Af    = sm + 32768;    // [2][8 k8][8 mt][32 lane][4]

    const int tid = threadIdx.x;
    const int warp = tid >> 5, lane = tid & 31;
    const int wm = warp >> 2;        // 0..1
    const int wn = warp & 3;         // 0..3
    const int m0 = blockIdx.x * 128;

    // copy B (already fragment-ordered, tf32 bits)
    #pragma unroll
    for (int i = 0; i < 32; i++) {
        int q = tid + i * 256;       // uint4 id 0..8191
        *(uint4*)(Bfull + q * 4) = *(const uint4*)((const uint32_t*)g_xsB + q * 4);
    }

    float d[4][4][4];
    #pragma unroll
    for (int i = 0; i < 4; i++)
        #pragma unroll
        for (int j = 0; j < 4; j++)
            #pragma unroll
            for (int q = 0; q < 4; q++) d[i][j][q] = 0.f;

    // A chunk loader (K-chunk kc: 128 rows x 64 k)
    float4 cur[8];
    auto loadA = [&](int kc, float4* A8) {
        #pragma unroll
        for (int it = 0; it < 8; it++) {
            int fid = tid + it * 256;         // 0..2047
            int r = fid >> 4, j = fid & 15;
            int row = m0 + r; if (row >= N) row = N - 1;
            A8[it] = *(const float4*)(E + (size_t)row * KDIM + kc * 64 + 4 * j);
        }
    };
    loadA(0, cur);

    for (int kc = 0; kc < 4; kc++) {
        const int buf = kc & 1;
        float4 nxt[8];
        if (kc < 3) loadA(kc + 1, nxt);

        uint32_t* Ab = Af + buf * 8192;
        #pragma unroll
        for (int it = 0; it < 8; it++) {
            int fid = tid + it * 256;
            int r = fid >> 4, j = fid & 15;
            int k8 = j >> 1, mt = r >> 4, mL = r & 15;
            uint32_t base = (uint32_t)((k8 * 8 + mt) * 32) * 4 + (mL >> 3) + 2 * (j & 1);
            const float* v = (const float*)&cur[it];
            #pragma unroll
            for (int q = 0; q < 4; q++)
                Ab[base + (uint32_t)((mL & 7) * 4 + q) * 4] = tf32r(v[q]);
        }
        __syncthreads();

        #pragma unroll
        for (int k8l = 0; k8l < 8; k8l++) {
            const int k8g = kc * 8 + k8l;
            uint32_t a[4][4], b[4][2];
            #pragma unroll
            for (int i = 0; i < 4; i++) {
                uint4 av = *(const uint4*)(Ab + ((k8l * 8 + wm * 4 + i) * 32 + lane) * 4);
                a[i][0] = av.x; a[i][1] = av.y; a[i][2] = av.z; a[i][3] = av.w;
            }
            #pragma unroll
            for (int j = 0; j < 4; j++) {
                uint2 bv = *(const uint2*)(Bfull + ((k8g * 16 + wn * 4 + j) * 32 + lane) * 2);
                b[j][0] = bv.x; b[j][1] = bv.y;
            }
            #pragma unroll
            for (int i = 0; i < 4; i++)
                #pragma unroll
                for (int j = 0; j < 4; j++)
                    mma8(d[i][j], a[i], b[j]);
        }
        __syncthreads();

        #pragma unroll
        for (int it = 0; it < 8; it++) cur[it] = nxt[it];
    }

    // epilogue
    const int rql = lane >> 2, cql = (lane & 3) * 2;
    #pragma unroll
    for (int i = 0; i < 4; i++) {
        int row = m0 + wm * 64 + i * 16 + rql;
        #pragma unroll
        for (int j = 0; j < 4; j++) {
            int col = wn * 32 + j * 8 + cql;
            if (row < N)
                *(float2*)(out + (size_t)row * CDIM + col) = make_float2(d[i][j][0], d[i][j][1]);
            if (row + 8 < N)
                *(float2*)(out + (size_t)(row + 8) * CDIM + col) = make_float2(d[i][j][2], d[i][j][3]);
        }
    }
}

// =====================================================================
extern "C" void kernel_launch(void* const* d_in, const int* in_sizes, int n_in,
                              void* d_out, int out_size)
{
    const float* evals = nullptr;
    const float* dt = nullptr;
    long big_a = -1, big_b = -1; int ia = -1, ib = -1;
    for (int i = 0; i < n_in; i++) {
        long sz = in_sizes[i];
        if (sz == 1)         dt = (const float*)d_in[i];
        else if (sz == KDIM) evals = (const float*)d_in[i];
        else {
            if (sz > big_a) { big_b = big_a; ib = ia; big_a = sz; ia = i; }
            else if (sz > big_b) { big_b = sz; ib = i; }
        }
    }
    const float* evecs = (const float*)d_in[ia];   // N*K (largest)
    const float* x     = (const float*)d_in[ib];   // N*C
    const int N = (int)(big_b / CDIM);

    static int cfg = 0;
    if (!cfg) {
        cudaFuncSetAttribute(phase1_kernel, cudaFuncAttributeMaxDynamicSharedMemorySize, 98304);
        cudaFuncSetAttribute(phase2_kernel, cudaFuncAttributeMaxDynamicSharedMemorySize, 196608);
        cfg = 1;
    }

    const int chunk = (N + P1_BLOCKS - 1) / P1_BLOCKS;
    phase1_kernel<<<P1_BLOCKS, 512, 98304>>>(evecs, x, N, chunk);
    reduce_kernel<<<(KDIM * CDIM) / 256, 256>>>(evals, dt);
    phase2_kernel<<<(N + 127) / 128, 256, 196608>>>(evecs, (float*)d_out, N);
}

// round 5
// speedup vs baseline: 2.9011x; 1.8839x over previous
#include <cuda_runtime.h>
#include <cuda_bf16.h>
#include <cstdint>
#include <math.h>

#define KDIM 256
#define CDIM 128
#define P1_BLOCKS 148

// Scratch (device globals; no allocation allowed)
__device__ float g_part[P1_BLOCKS * KDIM * CDIM];   // phase1 partials (fp32)
__device__ float g_xsB[KDIM * CDIM];                // spectrum in B-fragment layout (tf32 bits)

// ---------------- tf32 + mma helpers (sm_80-level PTX only) ----------------
__device__ __forceinline__ uint32_t tf32r(float x) {
    uint32_t u; asm("cvt.rna.tf32.f32 %0, %1;" : "=r"(u) : "f"(x)); return u;
}
__device__ __forceinline__ void mma8(float* d, const uint32_t* a, const uint32_t* b) {
    asm volatile(
        "mma.sync.aligned.m16n8k8.row.col.f32.tf32.tf32.f32 "
        "{%0,%1,%2,%3}, {%4,%5,%6,%7}, {%8,%9}, {%0,%1,%2,%3};"
        : "+f"(d[0]), "+f"(d[1]), "+f"(d[2]), "+f"(d[3])
        : "r"(a[0]), "r"(a[1]), "r"(a[2]), "r"(a[3]), "r"(b[0]), "r"(b[1]));
}

// Fragment maps (m16n8k8):
//  A value (mL 0..15, kL 0..7): lane = (mL%8)*4 + (kL%4), reg = mL/8 + 2*(kL/4)
//  B value (kL 0..7,  nL 0..7): lane = nL*4 + (kL%4),     reg = kL/4
//  D value: c0,c1 -> row=lane/4, col=2*(lane%4)+{0,1}; c2,c3 -> row+8

// ---- Padded fragment-tile strides (bank-conflict fix) ----
// Phase1 A: [4 k8][16 mt][32 lane][4 reg], mt stride 132 (128+4)
#define P1_AMT  132
#define P1_AK8  (16 * P1_AMT)       // 2112
#define P1_ABUF (4 * P1_AK8)        // 8448
// Phase1 B: [4 k8][16 ct][32 lane][2 reg], ct stride 66 (64+2)
#define P1_BCT  66
#define P1_BK8  (16 * P1_BCT)       // 1056
#define P1_BBUF (4 * P1_BK8)        // 4224
#define P1_SMEM ((2 * P1_ABUF + 2 * P1_BBUF) * 4)   // 101376 B

// Phase2 A: [8 k8][8 mt][32 lane][4 reg], k8 stride 1028 (1024+4)
#define P2_AK8  1028
#define P2_ABUF (8 * P2_AK8)        // 8224
#define P2_SMEM ((32768 + 2 * P2_ABUF) * 4)         // 196864 B

// =====================================================================
// Phase 1: partial[b] = evecs[nb:ne]^T @ x[nb:ne]  -> [256(k) x 128(c)]
// 512 threads = 16 warps (4m x 4n), warp tile 64x32, node-chunks of 32.
// =====================================================================
__global__ void __launch_bounds__(512, 1)
phase1_kernel(const float* __restrict__ E, const float* __restrict__ X,
              int N, int chunk)
{
    extern __shared__ uint32_t sm[];
    uint32_t* Af = sm;                    // 2 x P1_ABUF
    uint32_t* Bf = sm + 2 * P1_ABUF;      // 2 x P1_BBUF

    const int tid = threadIdx.x;
    const int warp = tid >> 5, lane = tid & 31;
    const int wm = warp >> 2;       // 0..3 -> m0 = wm*64
    const int wn = warp & 3;        // 0..3 -> n0 = wn*32

    float d[4][4][4];
    #pragma unroll
    for (int i = 0; i < 4; i++)
        #pragma unroll
        for (int j = 0; j < 4; j++)
            #pragma unroll
            for (int q = 0; q < 4; q++) d[i][j][q] = 0.f;

    const int nb = blockIdx.x * chunk;
    const int ne = min(N, nb + chunk);
    const int niter = (ne - nb + 31) >> 5;

    float4 curA[4], curB[2];

    auto loadc = [&](int s0, float4* A4, float4* B2) {
        #pragma unroll
        for (int it = 0; it < 4; it++) {
            int fid = tid + it * 512;         // 0..2047
            int r = fid >> 6, j = fid & 63;
            int node = s0 + r;
            A4[it] = (node < ne) ? *(const float4*)(E + (size_t)node * KDIM + 4 * j)
                                 : make_float4(0.f, 0.f, 0.f, 0.f);
        }
        #pragma unroll
        for (int it = 0; it < 2; it++) {
            int fid = tid + it * 512;         // 0..1023
            int r = fid >> 5, j = fid & 31;
            int node = s0 + r;
            B2[it] = (node < ne) ? *(const float4*)(X + (size_t)node * CDIM + 4 * j)
                                 : make_float4(0.f, 0.f, 0.f, 0.f);
        }
    };

    loadc(nb, curA, curB);

    for (int itn = 0; itn < niter; itn++) {
        const int buf = itn & 1;
        float4 nxtA[4], nxtB[2];
        if (itn + 1 < niter) loadc(nb + (itn + 1) * 32, nxtA, nxtB);

        uint32_t* Ab = Af + buf * P1_ABUF;
        uint32_t* Bb = Bf + buf * P1_BBUF;

        // A-frag scatter store (2-way max conflicts with padded strides)
        #pragma unroll
        for (int it = 0; it < 4; it++) {
            int fid = tid + it * 512;
            int r = fid >> 6, j = fid & 63;
            int k8 = r >> 3, kL = r & 7, mt = j >> 2;
            uint32_t base = (uint32_t)(k8 * P1_AK8 + mt * P1_AMT)
                          + ((j >> 1) & 1) + 2 * (kL >> 2);
            const float* v = (const float*)&curA[it];
            #pragma unroll
            for (int q = 0; q < 4; q++)
                Ab[base + (uint32_t)(16 * (j & 1) + 4 * q + (kL & 3)) * 4] = tf32r(v[q]);
        }
        // B-frag scatter store
        #pragma unroll
        for (int it = 0; it < 2; it++) {
            int fid = tid + it * 512;
            int r = fid >> 5, j = fid & 31;
            int k8 = r >> 3, kL = r & 7, ct = j >> 1;
            uint32_t base = (uint32_t)(k8 * P1_BK8 + ct * P1_BCT) + (kL >> 2);
            const float* v = (const float*)&curB[it];
            #pragma unroll
            for (int q = 0; q < 4; q++)
                Bb[base + (uint32_t)(16 * (j & 1) + 4 * q + (kL & 3)) * 2] = tf32r(v[q]);
        }
        __syncthreads();

        #pragma unroll
        for (int k8 = 0; k8 < 4; k8++) {
            uint32_t a[4][4], b[4][2];
            #pragma unroll
            for (int i = 0; i < 4; i++) {
                uint4 av = *(const uint4*)(Ab + k8 * P1_AK8 + (wm * 4 + i) * P1_AMT + lane * 4);
                a[i][0] = av.x; a[i][1] = av.y; a[i][2] = av.z; a[i][3] = av.w;
            }
            #pragma unroll
            for (int j = 0; j < 4; j++) {
                uint2 bv = *(const uint2*)(Bb + k8 * P1_BK8 + (wn * 4 + j) * P1_BCT + lane * 2);
                b[j][0] = bv.x; b[j][1] = bv.y;
            }
            #pragma unroll
            for (int i = 0; i < 4; i++)
                #pragma unroll
                for (int j = 0; j < 4; j++)
                    mma8(d[i][j], a[i], b[j]);
        }
        __syncthreads();

        #pragma unroll
        for (int it = 0; it < 4; it++) curA[it] = nxtA[it];
        curB[0] = nxtB[0]; curB[1] = nxtB[1];
    }

    float* base = g_part + (size_t)blockIdx.x * (KDIM * CDIM);
    const int rql = lane >> 2, cql = (lane & 3) * 2;
    #pragma unroll
    for (int i = 0; i < 4; i++) {
        int row = wm * 64 + i * 16 + rql;
        #pragma unroll
        for (int j = 0; j < 4; j++) {
            int col = wn * 32 + j * 8 + cql;
            *(float2*)(base + row * CDIM + col)       = make_float2(d[i][j][0], d[i][j][1]);
            *(float2*)(base + (row + 8) * CDIM + col) = make_float2(d[i][j][2], d[i][j][3]);
        }
    }
}

// =====================================================================
// Reduce: xs[k][c] = exp(-evals[k]*t) * sum_b part[b][k][c]
// Output in B-fragment layout (tf32 bits) for phase 2.
// =====================================================================
__global__ void reduce_kernel(const float* __restrict__ evals,
                              const float* __restrict__ dt)
{
    int idx = blockIdx.x * 256 + threadIdx.x;   // k*128 + c
    float s0 = 0.f, s1 = 0.f, s2 = 0.f, s3 = 0.f;
    int b = 0;
    for (; b + 4 <= P1_BLOCKS; b += 4) {
        s0 += g_part[(size_t)(b + 0) * (KDIM * CDIM) + idx];
        s1 += g_part[(size_t)(b + 1) * (KDIM * CDIM) + idx];
        s2 += g_part[(size_t)(b + 2) * (KDIM * CDIM) + idx];
        s3 += g_part[(size_t)(b + 3) * (KDIM * CDIM) + idx];
    }
    for (; b < P1_BLOCKS; b++) s0 += g_part[(size_t)b * (KDIM * CDIM) + idx];
    float s = (s0 + s1) + (s2 + s3);

    int k = idx >> 7, c = idx & 127;
    float t = fmaxf(dt[0], 1e-8f);
    float v = expf(-evals[k] * t) * s;

    int k8 = k >> 3, kL = k & 7, ct = c >> 3, cL = c & 7;
    uint32_t addr = (uint32_t)(((k8 * 16 + ct) * 32 + cL * 4 + (kL & 3)) * 2 + (kL >> 2));
    g_xsB[addr] = __uint_as_float(tf32r(v));
}

// =====================================================================
// Phase 2: out[m,c] = sum_k E[m,k] * xs[k,c]
// M-tile 128, N=128, K=256. 256 threads = 8 warps (2m x 4n).
// =====================================================================
__global__ void __launch_bounds__(256, 1)
phase2_kernel(const float* __restrict__ E, float* __restrict__ out, int N)
{
    extern __shared__ uint32_t sm[];
    uint32_t* Bfull = sm;            // [32 k8][16 ct][32 lane][2]  (32768 u32)
    uint32_t* Af    = sm + 32768;    // 2 x P2_ABUF

    const int tid = threadIdx.x;
    const int warp = tid >> 5, lane = tid & 31;
    const int wm = warp >> 2;        // 0..1
    const int wn = warp & 3;         // 0..3
    const int m0 = blockIdx.x * 128;

    #pragma unroll
    for (int i = 0; i < 32; i++) {
        int q = tid + i * 256;
        *(uint4*)(Bfull + q * 4) = *(const uint4*)((const uint32_t*)g_xsB + q * 4);
    }

    float d[4][4][4];
    #pragma unroll
    for (int i = 0; i < 4; i++)
        #pragma unroll
        for (int j = 0; j < 4; j++)
            #pragma unroll
            for (int q = 0; q < 4; q++) d[i][j][q] = 0.f;

    float4 cur[8];
    auto loadA = [&](int kc, float4* A8) {
        #pragma unroll
        for (int it = 0; it < 8; it++) {
            int fid = tid + it * 256;
            int r = fid >> 4, j = fid & 15;
            int row = m0 + r; if (row >= N) row = N - 1;
            A8[it] = *(const float4*)(E + (size_t)row * KDIM + kc * 64 + 4 * j);
        }
    };
    loadA(0, cur);

    for (int kc = 0; kc < 4; kc++) {
        const int buf = kc & 1;
        float4 nxt[8];
        if (kc < 3) loadA(kc + 1, nxt);

        uint32_t* Ab = Af + buf * P2_ABUF;
        #pragma unroll
        for (int it = 0; it < 8; it++) {
            int fid = tid + it * 256;
            int r = fid >> 4, j = fid & 15;
            int k8 = j >> 1, mt = r >> 4, mL = r & 15;
            uint32_t base = (uint32_t)(k8 * P2_AK8 + mt * 128)
                          + (mL >> 3) + 2 * (j & 1);
            const float* v = (const float*)&cur[it];
            #pragma unroll
            for (int q = 0; q < 4; q++)
                Ab[base + (uint32_t)((mL & 7) * 4 + q) * 4] = tf32r(v[q]);
        }
        __syncthreads();

        #pragma unroll
        for (int k8l = 0; k8l < 8; k8l++) {
            const int k8g = kc * 8 + k8l;
            uint32_t a[4][4], b[4][2];
            #pragma unroll
            for (int i = 0; i < 4; i++) {
                uint4 av = *(const uint4*)(Ab + k8l * P2_AK8 + (wm * 4 + i) * 128 + lane * 4);
                a[i][0] = av.x; a[i][1] = av.y; a[i][2] = av.z; a[i][3] = av.w;
            }
            #pragma unroll
            for (int j = 0; j < 4; j++) {
                uint2 bv = *(const uint2*)(Bfull + ((k8g * 16 + wn * 4 + j) * 32 + lane) * 2);
                b[j][0] = bv.x; b[j][1] = bv.y;
            }
            #pragma unroll
            for (int i = 0; i < 4; i++)
                #pragma unroll
                for (int j = 0; j < 4; j++)
                    mma8(d[i][j], a[i], b[j]);
        }
        __syncthreads();

        #pragma unroll
        for (int it = 0; it < 8; it++) cur[it] = nxt[it];
    }

    const int rql = lane >> 2, cql = (lane & 3) * 2;
    #pragma unroll
    for (int i = 0; i < 4; i++) {
        int row = m0 + wm * 64 + i * 16 + rql;
        #pragma unroll
        for (int j = 0; j < 4; j++) {
            int col = wn * 32 + j * 8 + cql;
            if (row < N)
                *(float2*)(out + (size_t)row * CDIM + col) = make_float2(d[i][j][0], d[i][j][1]);
            if (row + 8 < N)
                *(float2*)(out + (size_t)(row + 8) * CDIM + col) = make_float2(d[i][j][2], d[i][j][3]);
        }
    }
}

// =====================================================================
extern "C" void kernel_launch(void* const* d_in, const int* in_sizes, int n_in,
                              void* d_out, int out_size)
{
    const float* evals = nullptr;
    const float* dt = nullptr;
    long big_a = -1, big_b = -1; int ia = -1, ib = -1;
    for (int i = 0; i < n_in; i++) {
        long sz = in_sizes[i];
        if (sz == 1)         dt = (const float*)d_in[i];
        else if (sz == KDIM) evals = (const float*)d_in[i];
        else {
            if (sz > big_a) { big_b = big_a; ib = ia; big_a = sz; ia = i; }
            else if (sz > big_b) { big_b = sz; ib = i; }
        }
    }
    const float* evecs = (const float*)d_in[ia];   // N*K (largest)
    const float* x     = (const float*)d_in[ib];   // N*C
    const int N = (int)(big_b / CDIM);

    static int cfg = 0;
    if (!cfg) {
        cudaFuncSetAttribute(phase1_kernel, cudaFuncAttributeMaxDynamicSharedMemorySize, P1_SMEM);
        cudaFuncSetAttribute(phase2_kernel, cudaFuncAttributeMaxDynamicSharedMemorySize, P2_SMEM);
        cfg = 1;
    }

    const int chunk = (N + P1_BLOCKS - 1) / P1_BLOCKS;
    phase1_kernel<<<P1_BLOCKS, 512, P1_SMEM>>>(evecs, x, N, chunk);
    reduce_kernel<<<(KDIM * CDIM) / 256, 256>>>(evals, dt);
    phase2_kernel<<<(N + 127) / 128, 256, P2_SMEM>>>(evecs, (float*)d_out, N);
}